// round 16
// baseline (speedup 1.0000x reference)
#include <cuda_runtime.h>
#include <cuda_fp16.h>
#include <cstdint>
#include <math.h>

#define DIM   192
#define HEADS 6
#define HD    32
#define RLOW  128
#define NSEQ  3136
#define BATCH 32
#define MTOT  (BATCH * NSEQ)   // 100352

// ================= scratch (device globals, all fp16 single) =================
__device__ __align__(256) __half g_x[MTOT * DIM];            // x (window order)
__device__ __align__(256) __half g_q[MTOT * DIM];            // q, pre-scaled
__device__ __align__(256) __half g_kT[MTOT * DIM];           // K^T (b,c,n)
__device__ __align__(256) __half g_vT[MTOT * DIM];           // V^T (b,c,n)
__device__ __align__(256) __half g_a[MTOT * DIM];            // attn out (b,n,c)
__device__ __align__(256) __half g_kl[BATCH * RLOW * DIM];   // klow (b,R,c)
__device__ __align__(256) __half g_vlh[BATCH * DIM * RLOW];  // vlow^T (b,c,R)
__device__ __align__(256) __half g_wq[3 * DIM * DIM];
__device__ __align__(256) __half g_wp[DIM * DIM];
__device__ __align__(256) __half g_E[RLOW * NSEQ], g_F[RLOW * NSEQ];

// ================= helpers =================
__device__ __forceinline__ uint32_t smem_u32(const void* p) {
    uint32_t a;
    asm("{ .reg .u64 t; cvta.to.shared.u64 t, %1; cvt.u32.u64 %0, t; }" : "=r"(a) : "l"(p));
    return a;
}
__device__ __forceinline__ void ldsm4(uint32_t r[4], uint32_t a) {
    asm volatile("ldmatrix.sync.aligned.m8n8.x4.shared.b16 {%0,%1,%2,%3}, [%4];"
                 : "=r"(r[0]), "=r"(r[1]), "=r"(r[2]), "=r"(r[3]) : "r"(a));
}
__device__ __forceinline__ void mma16816h(float* c, const uint32_t a[4], uint32_t b0, uint32_t b1) {
    asm volatile("mma.sync.aligned.m16n8k16.row.col.f32.f16.f16.f32 "
                 "{%0,%1,%2,%3},{%4,%5,%6,%7},{%8,%9},{%0,%1,%2,%3};"
                 : "+f"(c[0]), "+f"(c[1]), "+f"(c[2]), "+f"(c[3])
                 : "r"(a[0]), "r"(a[1]), "r"(a[2]), "r"(a[3]), "r"(b0), "r"(b1));
}
__device__ __forceinline__ void cpa16(uint32_t saddr, const void* g) {
    asm volatile("cp.async.ca.shared.global [%0], [%1], 16;" :: "r"(saddr), "l"(g));
}
#define CPA_COMMIT() asm volatile("cp.async.commit_group;" ::: "memory")
#define CPA_WAIT1()  asm volatile("cp.async.wait_group 1;" ::: "memory")
#define CPA_WAIT0()  asm volatile("cp.async.wait_group 0;" ::: "memory")

__device__ __forceinline__ uint32_t pack_half2(float e0, float e1) {
    __half2 h = __floats2half2_rn(e0, e1);
    return *reinterpret_cast<uint32_t*>(&h);
}

// ================= unified GEMM smem layout =================
#define ROWB   80
#define SOFF   512
#define G_B    10240
#define G_STG  15360
#define SMEM_G (SOFF + 2 * G_STG)   // 31232
#define SMEM_PROJ 35328             // max(mainloop 31232, fp32 epilogue 512 + 128*272)

// 4 warps (2x2): warp tile 64x32. Per ks: A 4 ldsm + B 2 ldsm -> 16 mma.
__device__ __forceinline__ void chunk_64x32(uint32_t st, int wm, int wn, int lane,
                                            float acc[4][4][4])
{
    uint32_t a0r = st + (wm * 64 + (lane & 15)) * ROWB + ((lane >> 4) & 1) * 16;
    uint32_t b0r = st + G_B + (wn * 32 + (lane & 7) + ((lane >> 4) & 1) * 8) * ROWB
                   + ((lane >> 3) & 1) * 16;
#pragma unroll
    for (int ks = 0; ks < 2; ks++) {
        uint32_t a[4][4], bA[4], bB[4];
#pragma unroll
        for (int mf = 0; mf < 4; mf++)
            ldsm4(a[mf], a0r + mf * 16 * ROWB + ks * 32);
        ldsm4(bA, b0r + ks * 32);
        ldsm4(bB, b0r + 16 * ROWB + ks * 32);
        uint32_t bb[4][2] = {{bA[0], bA[1]}, {bA[2], bA[3]}, {bB[0], bB[1]}, {bB[2], bB[3]}};
#pragma unroll
        for (int mf = 0; mf < 4; mf++)
#pragma unroll
            for (int nf = 0; nf < 4; nf++)
                mma16816h(acc[mf][nf], a[mf], bb[nf][0], bb[nf][1]);
    }
}

// ================= fused conversion =================
#define N4X (MTOT * DIM / 4)
#define N4Q (3 * DIM * DIM / 4)
#define N4E (RLOW * NSEQ / 4)
#define N4P (DIM * DIM / 4)
#define N4TOT (N4X + N4Q + 2 * N4E + N4P)
__global__ void split_all(const float* __restrict__ x, const float* __restrict__ qw,
                          const float* __restrict__ Ew, const float* __restrict__ Fw,
                          const float* __restrict__ pw)
{
    int i = blockIdx.x * blockDim.x + threadIdx.x;
    if (i >= N4TOT) return;
    const float* src;
    __half* dst;
    int off;
    if (i < N4X)                       { src = x;  dst = g_x;  off = i; }
    else if (i < N4X + N4Q)            { src = qw; dst = g_wq; off = i - N4X; }
    else if (i < N4X + N4Q + N4E)      { src = Ew; dst = g_E;  off = i - N4X - N4Q; }
    else if (i < N4X + N4Q + 2 * N4E)  { src = Fw; dst = g_F;  off = i - N4X - N4Q - N4E; }
    else                               { src = pw; dst = g_wp; off = i - N4X - N4Q - 2 * N4E; }
    float4 v = reinterpret_cast<const float4*>(src)[off];
    reinterpret_cast<__half2*>(dst)[2 * off]     = __floats2half2_rn(v.x, v.y);
    reinterpret_cast<__half2*>(dst)[2 * off + 1] = __floats2half2_rn(v.z, v.w);
}

// ================= QKV: M=128 N=64 K=192, 128 threads =================
__global__ __launch_bounds__(128, 4) void qkv_mma(const float* __restrict__ bias)
{
    extern __shared__ char sm[];
    uint32_t sb = smem_u32(sm);
    const int t = threadIdx.x, lane = t & 31, wid = t >> 5;
    const int wm = wid & 1, wn = wid >> 1;
    const int m0 = blockIdx.x * 128, j0 = blockIdx.y * 64;
    int* rowoff = (int*)sm;

    {
        int m   = m0 + t;
        int bb  = m / NSEQ, n = m - bb * NSEQ;
        int r56 = n / 56, c56 = n - r56 * 56;
        int hb  = r56 / 7, hi_ = r56 - hb * 7;
        int wb  = c56 / 7, wi = c56 - wb * 7;
        rowoff[t] = ((bb * 64 + hb * 8 + wb) * 49 + hi_ * 7 + wi) * DIM;
    }
    __syncthreads();

    auto issue = [&](int i) {
        uint32_t st = sb + SOFF + (i & 1) * G_STG;
        int k0 = i * 32;
#pragma unroll
        for (int l = 0; l < 4; l++) {
            int idx = t + 128 * l;
            int row = idx >> 2, cg = idx & 3;
            cpa16(st + row * ROWB + cg * 16, g_x + rowoff[row] + k0 + cg * 8);
        }
#pragma unroll
        for (int l = 0; l < 2; l++) {
            int idx = t + 128 * l;
            int row = idx >> 2, cg = idx & 3;
            cpa16(st + G_B + row * ROWB + cg * 16, g_wq + (j0 + row) * DIM + k0 + cg * 8);
        }
        CPA_COMMIT();
    };

    float acc[4][4][4] = {};
    issue(0);
    for (int i = 0; i < 6; i++) {
        if (i < 5) { issue(i + 1); CPA_WAIT1(); } else { CPA_WAIT0(); }
        __syncthreads();
        chunk_64x32(sb + SOFF + (i & 1) * G_STG, wm, wn, lane, acc);
        __syncthreads();
    }

    const int seg = j0 / DIM;          // 0=q 1=k 2=v
    const int jb  = j0 - seg * DIM;
    const float scale = 0.17677669529663687f;

    if (seg == 0) {
#pragma unroll
        for (int mf = 0; mf < 4; mf++)
#pragma unroll
            for (int rr = 0; rr < 2; rr++) {
                int ml = wm * 64 + mf * 16 + (lane >> 2) + rr * 8;
#pragma unroll
                for (int nf = 0; nf < 4; nf++)
#pragma unroll
                    for (int cp = 0; cp < 2; cp++) {
                        int c = wn * 32 + nf * 8 + (lane & 3) * 2 + cp;
                        float v = (acc[mf][nf][rr * 2 + cp] + bias[j0 + c]) * scale;
                        *(__half*)(sm + SOFF + ml * 144 + c * 2) = __float2half(v);
                    }
            }
        __syncthreads();
        const int h0 = jb >> 5;
#pragma unroll
        for (int l = 0; l < 2; l++) {
            int idx = t + 128 * l;
            int row = idx >> 1, qq = idx & 1;
            int m = m0 + row, b = m / NSEQ, n = m - b * NSEQ;
            const uint4* src = (const uint4*)(sm + SOFF + row * 144 + qq * 64);
            __half* dst = g_q + ((b * HEADS + h0 + qq) * NSEQ + n) * HD;
#pragma unroll
            for (int u = 0; u < 4; u++) ((uint4*)dst)[u] = src[u];
        }
    } else {
#pragma unroll
        for (int mf = 0; mf < 4; mf++)
#pragma unroll
            for (int rr = 0; rr < 2; rr++) {
                int ml = wm * 64 + mf * 16 + (lane >> 2) + rr * 8;
#pragma unroll
                for (int nf = 0; nf < 4; nf++)
#pragma unroll
                    for (int cp = 0; cp < 2; cp++) {
                        int c = wn * 32 + nf * 8 + (lane & 3) * 2 + cp;
                        float v = acc[mf][nf][rr * 2 + cp] + bias[j0 + c];
                        *(__half*)(sm + SOFF + c * 272 + ml * 2) = __float2half(v);
                    }
            }
        __syncthreads();
        __half* T = (seg == 1) ? g_kT : g_vT;
#pragma unroll
        for (int l = 0; l < 8; l++) {
            int idx = t + 128 * l;
            int c = idx >> 4, g = idx & 15;
            int m = m0 + g * 8, b = m / NSEQ, n = m - b * NSEQ;
            uint4 v = *(const uint4*)(sm + SOFF + c * 272 + g * 16);
            *(uint4*)(T + (b * DIM + jb + c) * NSEQ + n) = v;
        }
    }
}

// ================= low-rank: M=128 N=64 K=3136, 128 threads =================
__global__ __launch_bounds__(128, 4) void lowrank_mma(const float* __restrict__ Eb,
                                                      const float* __restrict__ Fb)
{
    extern __shared__ char sm[];
    uint32_t sb = smem_u32(sm);
    const int t = threadIdx.x, lane = t & 31, wid = t >> 5;
    const int wm = wid & 1, wn = wid >> 1;
    const int c0 = blockIdx.x * 64, b = blockIdx.y, which = blockIdx.z;

    const __half* A  = which ? g_F : g_E;
    const __half* Bm = which ? g_vT : g_kT;
    const float* bias = which ? Fb : Eb;

    auto issue = [&](int i) {
        uint32_t st = sb + SOFF + (i & 1) * G_STG;
        int k0 = i * 32;
#pragma unroll
        for (int l = 0; l < 4; l++) {
            int idx = t + 128 * l;
            int row = idx >> 2, cg = idx & 3;
            cpa16(st + row * ROWB + cg * 16, A + row * NSEQ + k0 + cg * 8);
        }
#pragma unroll
        for (int l = 0; l < 2; l++) {
            int idx = t + 128 * l;
            int row = idx >> 2, cg = idx & 3;
            cpa16(st + G_B + row * ROWB + cg * 16,
                  Bm + (b * DIM + c0 + row) * NSEQ + k0 + cg * 8);
        }
        CPA_COMMIT();
    };

    float acc[4][4][4] = {};
    issue(0);
    for (int i = 0; i < 98; i++) {
        if (i < 97) { issue(i + 1); CPA_WAIT1(); } else { CPA_WAIT0(); }
        __syncthreads();
        chunk_64x32(sb + SOFF + (i & 1) * G_STG, wm, wn, lane, acc);
        __syncthreads();
    }

    if (which == 0) {
#pragma unroll
        for (int mf = 0; mf < 4; mf++)
#pragma unroll
            for (int rr = 0; rr < 2; rr++) {
                int r = wm * 64 + mf * 16 + (lane >> 2) + rr * 8;
                float bv = bias[r];
#pragma unroll
                for (int nf = 0; nf < 4; nf++)
#pragma unroll
                    for (int cp = 0; cp < 2; cp++) {
                        int c = wn * 32 + nf * 8 + (lane & 3) * 2 + cp;
                        *(__half*)(sm + SOFF + r * 144 + c * 2) =
                            __float2half(acc[mf][nf][rr * 2 + cp] + bv);
                    }
            }
        __syncthreads();
#pragma unroll
        for (int l = 0; l < 2; l++) {
            int idx = t + 128 * l;
            int r = idx >> 1, half = idx & 1;
            const uint4* src = (const uint4*)(sm + SOFF + r * 144 + half * 64);
            __half* dst = g_kl + (b * RLOW + r) * DIM + c0 + half * 32;
#pragma unroll
            for (int u = 0; u < 4; u++) ((uint4*)dst)[u] = src[u];
        }
    } else {
#pragma unroll
        for (int mf = 0; mf < 4; mf++)
#pragma unroll
            for (int rr = 0; rr < 2; rr++) {
                int r = wm * 64 + mf * 16 + (lane >> 2) + rr * 8;
                float bv = bias[r];
#pragma unroll
                for (int nf = 0; nf < 4; nf++)
#pragma unroll
                    for (int cp = 0; cp < 2; cp++) {
                        int c = wn * 32 + nf * 8 + (lane & 3) * 2 + cp;
                        *(__half*)(sm + SOFF + c * 272 + r * 2) =
                            __float2half(acc[mf][nf][rr * 2 + cp] + bv);
                    }
            }
        __syncthreads();
#pragma unroll
        for (int l = 0; l < 8; l++) {
            int idx = t + 128 * l;
            int c = idx >> 4, g = idx & 15;
            uint4 v = *(const uint4*)(sm + SOFF + c * 272 + g * 16);
            *(uint4*)(g_vlh + (b * DIM + c0 + c) * RLOW + g * 8) = v;
        }
    }
}

// ================= attention: 2 warps x 32 rows, 1-term fp16 =================
#define AQ 0
#define AK 5120
#define AV 15360
#define ATT_SMEM 24064
__global__ __launch_bounds__(64) void attn_mma()
{
    extern __shared__ char sm[];
    uint32_t sb = smem_u32(sm);
    const int t = threadIdx.x, lane = t & 31, w = t >> 5;
    const int n0 = blockIdx.x * 64, hh = blockIdx.y, b = blockIdx.z;

    {
        const __half* qh = g_q + ((b * HEADS + hh) * NSEQ + n0) * HD;
#pragma unroll
        for (int l = 0; l < 4; l++) {
            int idx = t + 64 * l;               // 256 uint4: 64 rows x 4
            int row = idx >> 2, cg = idx & 3;
            *(uint4*)(sm + AQ + row * 80 + cg * 16) = *(const uint4*)(qh + row * HD + cg * 8);
        }
        const __half* kh = g_kl + b * RLOW * DIM + hh * HD;
#pragma unroll
        for (int l = 0; l < 8; l++) {
            int idx = t + 64 * l;               // 512 uint4: 128 rows x 4
            int row = idx >> 2, cg = idx & 3;
            *(uint4*)(sm + AK + row * 80 + cg * 16) = *(const uint4*)(kh + row * DIM + cg * 8);
        }
        const __half* vh = g_vlh + (b * DIM + hh * HD) * RLOW;
#pragma unroll
        for (int l = 0; l < 8; l++) {
            int idx = t + 64 * l;               // 512 uint4: 32 rows x 16
            int row = idx >> 4, cg = idx & 15;
            *(uint4*)(sm + AV + row * 272 + cg * 16) = *(const uint4*)(vh + row * RLOW + cg * 8);
        }
    }
    __syncthreads();

    // phase 1: logits[mf 0..1][np2 0..15][4], rows = w*32 + mf*16 + gr(+8)
    float acc[2][16][4] = {};
    {
        uint32_t qa = sb + AQ + (w * 32 + (lane & 15)) * 80 + ((lane >> 4) & 1) * 16;
        uint32_t ba = sb + AK + ((lane & 7) + ((lane >> 4) & 1) * 8) * 80 + ((lane >> 3) & 1) * 16;
#pragma unroll
        for (int ks = 0; ks < 2; ks++) {
            uint32_t a0[4], a1[4];
            ldsm4(a0, qa + ks * 32);
            ldsm4(a1, qa + 16 * 80 + ks * 32);
#pragma unroll
            for (int np = 0; np < 8; np++) {
                uint32_t bh[4];
                ldsm4(bh, ba + np * 1280 + ks * 32);
                mma16816h(acc[0][2 * np],     a0, bh[0], bh[1]);
                mma16816h(acc[0][2 * np + 1], a0, bh[2], bh[3]);
                mma16816h(acc[1][2 * np],     a1, bh[0], bh[1]);
                mma16816h(acc[1][2 * np + 1], a1, bh[2], bh[3]);
            }
        }
    }

    // softmax over 4 row-groups: g = 2*mf + (pair), rows mf*16 + gr (+8)
    float mx[4] = {-1e30f, -1e30f, -1e30f, -1e30f};
#pragma unroll
    for (int mf = 0; mf < 2; mf++)
#pragma unroll
        for (int i = 0; i < 16; i++) {
            mx[2 * mf]     = fmaxf(mx[2 * mf],     fmaxf(acc[mf][i][0], acc[mf][i][1]));
            mx[2 * mf + 1] = fmaxf(mx[2 * mf + 1], fmaxf(acc[mf][i][2], acc[mf][i][3]));
        }
#pragma unroll
    for (int g = 0; g < 4; g++) {
        mx[g] = fmaxf(mx[g], __shfl_xor_sync(0xffffffff, mx[g], 1));
        mx[g] = fmaxf(mx[g], __shfl_xor_sync(0xffffffff, mx[g], 2));
    }
    float sum[4] = {0.f, 0.f, 0.f, 0.f};
#pragma unroll
    for (int mf = 0; mf < 2; mf++)
#pragma unroll
        for (int i = 0; i < 16; i++) {
            acc[mf][i][0] = __expf(acc[mf][i][0] - mx[2 * mf]);     sum[2 * mf]     += acc[mf][i][0];
            acc[mf][i][1] = __expf(acc[mf][i][1] - mx[2 * mf]);     sum[2 * mf]     += acc[mf][i][1];
            acc[mf][i][2] = __expf(acc[mf][i][2] - mx[2 * mf + 1]); sum[2 * mf + 1] += acc[mf][i][2];
            acc[mf][i][3] = __expf(acc[mf][i][3] - mx[2 * mf + 1]); sum[2 * mf + 1] += acc[mf][i][3];
        }
#pragma unroll
    for (int g = 0; g < 4; g++) {
        sum[g] += __shfl_xor_sync(0xffffffff, sum[g], 1);
        sum[g] += __shfl_xor_sync(0xffffffff, sum[g], 2);
    }

    // phase 3: out = a_fp16 @ v_fp16, oacc[mf][nf][4]
    float oacc[2][4][4] = {};
    {
        uint32_t va = sb + AV + ((lane & 7) + ((lane >> 4) & 1) * 8) * 272 + ((lane >> 3) & 1) * 16;
#pragma unroll
        for (int kt = 0; kt < 8; kt++) {
            uint32_t ah[2][4];
#pragma unroll
            for (int mf = 0; mf < 2; mf++) {
                ah[mf][0] = pack_half2(acc[mf][2 * kt][0],     acc[mf][2 * kt][1]);
                ah[mf][1] = pack_half2(acc[mf][2 * kt][2],     acc[mf][2 * kt][3]);
                ah[mf][2] = pack_half2(acc[mf][2 * kt + 1][0], acc[mf][2 * kt + 1][1]);
                ah[mf][3] = pack_half2(acc[mf][2 * kt + 1][2], acc[mf][2 * kt + 1][3]);
            }
#pragma unroll
            for (int np = 0; np < 2; np++) {
                uint32_t vh[4];
                ldsm4(vh, va + np * 16 * 272 + kt * 32);
#pragma unroll
                for (int mf = 0; mf < 2; mf++) {
                    mma16816h(oacc[mf][2 * np],     ah[mf], vh[0], vh[1]);
                    mma16816h(oacc[mf][2 * np + 1], ah[mf], vh[2], vh[3]);
                }
            }
        }
    }

    // epilogue
    {
        int gr = lane >> 2;
        int cbase = hh * HD + (lane & 3) * 2;
#pragma unroll
        for (int mf = 0; mf < 2; mf++) {
            float inv0 = 1.0f / sum[2 * mf], inv1 = 1.0f / sum[2 * mf + 1];
            int row0 = n0 + w * 32 + mf * 16 + gr, row1 = row0 + 8;
#pragma unroll
            for (int nf = 0; nf < 4; nf++) {
                int col = cbase + nf * 8;
                *(uint32_t*)(g_a + (b * NSEQ + row0) * DIM + col) =
                    pack_half2(oacc[mf][nf][0] * inv0, oacc[mf][nf][1] * inv0);
                *(uint32_t*)(g_a + (b * NSEQ + row1) * DIM + col) =
                    pack_half2(oacc[mf][nf][2] * inv1, oacc[mf][nf][3] * inv1);
            }
        }
    }
}

// ================= proj: M=128 N=64 K=192, 128 threads (SMEM_PROJ) =================
__global__ __launch_bounds__(128, 4) void proj_mma(const float* __restrict__ bias,
                                                   float* __restrict__ out)
{
    extern __shared__ char sm[];
    uint32_t sb = smem_u32(sm);
    const int t = threadIdx.x, lane = t & 31, wid = t >> 5;
    const int wm = wid & 1, wn = wid >> 1;
    const int m0 = blockIdx.x * 128, j0 = blockIdx.y * 64;

    auto issue = [&](int i) {
        uint32_t st = sb + SOFF + (i & 1) * G_STG;
        int k0 = i * 32;
#pragma unroll
        for (int l = 0; l < 4; l++) {
            int idx = t + 128 * l;
            int row = idx >> 2, cg = idx & 3;
            cpa16(st + row * ROWB + cg * 16, g_a + (m0 + row) * DIM + k0 + cg * 8);
        }
#pragma unroll
        for (int l = 0; l < 2; l++) {
            int idx = t + 128 * l;
            int row = idx >> 2, cg = idx & 3;
            cpa16(st + G_B + row * ROWB + cg * 16, g_wp + (j0 + row) * DIM + k0 + cg * 8);
        }
        CPA_COMMIT();
    };

    float acc[4][4][4] = {};
    issue(0);
    for (int i = 0; i < 6; i++) {
        if (i < 5) { issue(i + 1); CPA_WAIT1(); } else { CPA_WAIT0(); }
        __syncthreads();
        chunk_64x32(sb + SOFF + (i & 1) * G_STG, wm, wn, lane, acc);
        __syncthreads();
    }

#pragma unroll
    for (int mf = 0; mf < 4; mf++)
#pragma unroll
        for (int rr = 0; rr < 2; rr++) {
            int ml = wm * 64 + mf * 16 + (lane >> 2) + rr * 8;
#pragma unroll
            for (int nf = 0; nf < 4; nf++)
#pragma unroll
                for (int cp = 0; cp < 2; cp++) {
                    int c = wn * 32 + nf * 8 + (lane & 3) * 2 + cp;
                    *(float*)(sm + SOFF + ml * 272 + c * 4) =
                        acc[mf][nf][rr * 2 + cp] + bias[j0 + c];
                }
        }
    __syncthreads();
#pragma unroll
    for (int l = 0; l < 16; l++) {
        int idx = t + 128 * l;
        int row = idx >> 4, g = idx & 15;
        uint4 v = *(const uint4*)(sm + SOFF + row * 272 + g * 16);
        *(uint4*)(out + (m0 + row) * DIM + j0 + g * 4) = v;
    }
}

// ================= host =================
extern "C" void kernel_launch(void* const* d_in, const int* in_sizes, int n_in,
                              void* d_out, int out_size)
{
    const float* x      = (const float*)d_in[0];
    const float* qkv_w  = (const float*)d_in[1];
    const float* qkv_b  = (const float*)d_in[2];
    const float* E_w    = (const float*)d_in[3];
    const float* E_b    = (const float*)d_in[4];
    const float* F_w    = (const float*)d_in[5];
    const float* F_b    = (const float*)d_in[6];
    const float* proj_w = (const float*)d_in[7];
    const float* proj_b = (const float*)d_in[8];
    float* out = (float*)d_out;

    cudaFuncSetAttribute(qkv_mma, cudaFuncAttributeMaxDynamicSharedMemorySize, SMEM_G);
    cudaFuncSetAttribute(lowrank_mma, cudaFuncAttributeMaxDynamicSharedMemorySize, SMEM_G);
    cudaFuncSetAttribute(proj_mma, cudaFuncAttributeMaxDynamicSharedMemorySize, SMEM_PROJ);
    cudaFuncSetAttribute(attn_mma, cudaFuncAttributeMaxDynamicSharedMemorySize, ATT_SMEM);

    split_all<<<(N4TOT + 255) / 256, 256>>>(x, qkv_w, E_w, F_w, proj_w);
    qkv_mma<<<dim3(MTOT / 128, 9), 128, SMEM_G>>>(qkv_b);
    lowrank_mma<<<dim3(3, BATCH, 2), 128, SMEM_G>>>(E_b, F_b);
    attn_mma<<<dim3(NSEQ / 64, HEADS, BATCH), 64, ATT_SMEM>>>();
    proj_mma<<<dim3(MTOT / 128, 3), 128, SMEM_PROJ>>>(proj_b, out);
}

// round 17
// speedup vs baseline: 1.0608x; 1.0608x over previous
#include <cuda_runtime.h>
#include <cuda_fp16.h>
#include <cstdint>
#include <math.h>

#define DIM   192
#define HEADS 6
#define HD    32
#define RLOW  128
#define NSEQ  3136
#define BATCH 32
#define MTOT  (BATCH * NSEQ)   // 100352

// ================= scratch (device globals, all fp16 single) =================
__device__ __align__(256) __half g_x[MTOT * DIM];            // x (window order)
__device__ __align__(256) __half g_q[MTOT * DIM];            // q, pre-scaled
__device__ __align__(256) __half g_kT[MTOT * DIM];           // K^T (b,c,n)
__device__ __align__(256) __half g_vT[MTOT * DIM];           // V^T (b,c,n)
__device__ __align__(256) __half g_a[MTOT * DIM];            // attn out (b,n,c)
__device__ __align__(256) __half g_kl[BATCH * RLOW * DIM];   // klow (b,R,c)
__device__ __align__(256) __half g_vlh[BATCH * DIM * RLOW];  // vlow^T (b,c,R)
__device__ __align__(256) __half g_wq[3 * DIM * DIM];
__device__ __align__(256) __half g_wp[DIM * DIM];
__device__ __align__(256) __half g_E[RLOW * NSEQ], g_F[RLOW * NSEQ];

// ================= helpers =================
__device__ __forceinline__ uint32_t smem_u32(const void* p) {
    uint32_t a;
    asm("{ .reg .u64 t; cvta.to.shared.u64 t, %1; cvt.u32.u64 %0, t; }" : "=r"(a) : "l"(p));
    return a;
}
__device__ __forceinline__ void ldsm4(uint32_t r[4], uint32_t a) {
    asm volatile("ldmatrix.sync.aligned.m8n8.x4.shared.b16 {%0,%1,%2,%3}, [%4];"
                 : "=r"(r[0]), "=r"(r[1]), "=r"(r[2]), "=r"(r[3]) : "r"(a));
}
__device__ __forceinline__ void mma16816h(float* c, const uint32_t a[4], uint32_t b0, uint32_t b1) {
    asm volatile("mma.sync.aligned.m16n8k16.row.col.f32.f16.f16.f32 "
                 "{%0,%1,%2,%3},{%4,%5,%6,%7},{%8,%9},{%0,%1,%2,%3};"
                 : "+f"(c[0]), "+f"(c[1]), "+f"(c[2]), "+f"(c[3])
                 : "r"(a[0]), "r"(a[1]), "r"(a[2]), "r"(a[3]), "r"(b0), "r"(b1));
}
__device__ __forceinline__ void cpa16(uint32_t saddr, const void* g) {
    asm volatile("cp.async.ca.shared.global [%0], [%1], 16;" :: "r"(saddr), "l"(g));
}
#define CPA_COMMIT() asm volatile("cp.async.commit_group;" ::: "memory")
#define CPA_WAIT1()  asm volatile("cp.async.wait_group 1;" ::: "memory")
#define CPA_WAIT0()  asm volatile("cp.async.wait_group 0;" ::: "memory")

__device__ __forceinline__ uint32_t pack_half2(float e0, float e1) {
    __half2 h = __floats2half2_rn(e0, e1);
    return *reinterpret_cast<uint32_t*>(&h);
}

// ================= unified GEMM smem layout =================
#define ROWB   80
#define SOFF   512
#define G_B    10240
#define G_STG  15360
#define SMEM_G (SOFF + 2 * G_STG)    // 31232
#define SMEM_LR (SOFF + 3 * G_STG)   // 46592 (3-stage lowrank)
#define SMEM_PROJ 35328              // max(mainloop 31232, fp32 epilogue 512 + 128*272)

// 4 warps (2x2): warp tile 64x32. Per ks: A 4 ldsm + B 2 ldsm -> 16 mma.
__device__ __forceinline__ void chunk_64x32(uint32_t st, int wm, int wn, int lane,
                                            float acc[4][4][4])
{
    uint32_t a0r = st + (wm * 64 + (lane & 15)) * ROWB + ((lane >> 4) & 1) * 16;
    uint32_t b0r = st + G_B + (wn * 32 + (lane & 7) + ((lane >> 4) & 1) * 8) * ROWB
                   + ((lane >> 3) & 1) * 16;
#pragma unroll
    for (int ks = 0; ks < 2; ks++) {
        uint32_t a[4][4], bA[4], bB[4];
#pragma unroll
        for (int mf = 0; mf < 4; mf++)
            ldsm4(a[mf], a0r + mf * 16 * ROWB + ks * 32);
        ldsm4(bA, b0r + ks * 32);
        ldsm4(bB, b0r + 16 * ROWB + ks * 32);
        uint32_t bb[4][2] = {{bA[0], bA[1]}, {bA[2], bA[3]}, {bB[0], bB[1]}, {bB[2], bB[3]}};
#pragma unroll
        for (int mf = 0; mf < 4; mf++)
#pragma unroll
            for (int nf = 0; nf < 4; nf++)
                mma16816h(acc[mf][nf], a[mf], bb[nf][0], bb[nf][1]);
    }
}

// ================= fused conversion =================
#define N4X (MTOT * DIM / 4)
#define N4Q (3 * DIM * DIM / 4)
#define N4E (RLOW * NSEQ / 4)
#define N4P (DIM * DIM / 4)
#define N4TOT (N4X + N4Q + 2 * N4E + N4P)
__global__ void split_all(const float* __restrict__ x, const float* __restrict__ qw,
                          const float* __restrict__ Ew, const float* __restrict__ Fw,
                          const float* __restrict__ pw)
{
    int i = blockIdx.x * blockDim.x + threadIdx.x;
    if (i >= N4TOT) return;
    const float* src;
    __half* dst;
    int off;
    if (i < N4X)                       { src = x;  dst = g_x;  off = i; }
    else if (i < N4X + N4Q)            { src = qw; dst = g_wq; off = i - N4X; }
    else if (i < N4X + N4Q + N4E)      { src = Ew; dst = g_E;  off = i - N4X - N4Q; }
    else if (i < N4X + N4Q + 2 * N4E)  { src = Fw; dst = g_F;  off = i - N4X - N4Q - N4E; }
    else                               { src = pw; dst = g_wp; off = i - N4X - N4Q - 2 * N4E; }
    float4 v = reinterpret_cast<const float4*>(src)[off];
    reinterpret_cast<__half2*>(dst)[2 * off]     = __floats2half2_rn(v.x, v.y);
    reinterpret_cast<__half2*>(dst)[2 * off + 1] = __floats2half2_rn(v.z, v.w);
}

// ================= QKV: M=128 N=64 K=192, 128 threads (R15-proven) =================
__global__ __launch_bounds__(128, 4) void qkv_mma(const float* __restrict__ bias)
{
    extern __shared__ char sm[];
    uint32_t sb = smem_u32(sm);
    const int t = threadIdx.x, lane = t & 31, wid = t >> 5;
    const int wm = wid & 1, wn = wid >> 1;
    const int m0 = blockIdx.x * 128, j0 = blockIdx.y * 64;
    int* rowoff = (int*)sm;

    {
        int m   = m0 + t;
        int bb  = m / NSEQ, n = m - bb * NSEQ;
        int r56 = n / 56, c56 = n - r56 * 56;
        int hb  = r56 / 7, hi_ = r56 - hb * 7;
        int wb  = c56 / 7, wi = c56 - wb * 7;
        rowoff[t] = ((bb * 64 + hb * 8 + wb) * 49 + hi_ * 7 + wi) * DIM;
    }
    __syncthreads();

    auto issue = [&](int i) {
        uint32_t st = sb + SOFF + (i & 1) * G_STG;
        int k0 = i * 32;
#pragma unroll
        for (int l = 0; l < 4; l++) {
            int idx = t + 128 * l;
            int row = idx >> 2, cg = idx & 3;
            cpa16(st + row * ROWB + cg * 16, g_x + rowoff[row] + k0 + cg * 8);
        }
#pragma unroll
        for (int l = 0; l < 2; l++) {
            int idx = t + 128 * l;
            int row = idx >> 2, cg = idx & 3;
            cpa16(st + G_B + row * ROWB + cg * 16, g_wq + (j0 + row) * DIM + k0 + cg * 8);
        }
        CPA_COMMIT();
    };

    float acc[4][4][4] = {};
    issue(0);
    for (int i = 0; i < 6; i++) {
        if (i < 5) { issue(i + 1); CPA_WAIT1(); } else { CPA_WAIT0(); }
        __syncthreads();
        chunk_64x32(sb + SOFF + (i & 1) * G_STG, wm, wn, lane, acc);
        __syncthreads();
    }

    const int seg = j0 / DIM;          // 0=q 1=k 2=v
    const int jb  = j0 - seg * DIM;
    const float scale = 0.17677669529663687f;

    if (seg == 0) {
#pragma unroll
        for (int mf = 0; mf < 4; mf++)
#pragma unroll
            for (int rr = 0; rr < 2; rr++) {
                int ml = wm * 64 + mf * 16 + (lane >> 2) + rr * 8;
#pragma unroll
                for (int nf = 0; nf < 4; nf++)
#pragma unroll
                    for (int cp = 0; cp < 2; cp++) {
                        int c = wn * 32 + nf * 8 + (lane & 3) * 2 + cp;
                        float v = (acc[mf][nf][rr * 2 + cp] + bias[j0 + c]) * scale;
                        *(__half*)(sm + SOFF + ml * 144 + c * 2) = __float2half(v);
                    }
            }
        __syncthreads();
        const int h0 = jb >> 5;
#pragma unroll
        for (int l = 0; l < 2; l++) {
            int idx = t + 128 * l;
            int row = idx >> 1, qq = idx & 1;
            int m = m0 + row, b = m / NSEQ, n = m - b * NSEQ;
            const uint4* src = (const uint4*)(sm + SOFF + row * 144 + qq * 64);
            __half* dst = g_q + ((b * HEADS + h0 + qq) * NSEQ + n) * HD;
#pragma unroll
            for (int u = 0; u < 4; u++) ((uint4*)dst)[u] = src[u];
        }
    } else {
#pragma unroll
        for (int mf = 0; mf < 4; mf++)
#pragma unroll
            for (int rr = 0; rr < 2; rr++) {
                int ml = wm * 64 + mf * 16 + (lane >> 2) + rr * 8;
#pragma unroll
                for (int nf = 0; nf < 4; nf++)
#pragma unroll
                    for (int cp = 0; cp < 2; cp++) {
                        int c = wn * 32 + nf * 8 + (lane & 3) * 2 + cp;
                        float v = acc[mf][nf][rr * 2 + cp] + bias[j0 + c];
                        *(__half*)(sm + SOFF + c * 272 + ml * 2) = __float2half(v);
                    }
            }
        __syncthreads();
        __half* T = (seg == 1) ? g_kT : g_vT;
#pragma unroll
        for (int l = 0; l < 8; l++) {
            int idx = t + 128 * l;
            int c = idx >> 4, g = idx & 15;
            int m = m0 + g * 8, b = m / NSEQ, n = m - b * NSEQ;
            uint4 v = *(const uint4*)(sm + SOFF + c * 272 + g * 16);
            *(uint4*)(T + (b * DIM + jb + c) * NSEQ + n) = v;
        }
    }
}

// ================= low-rank: M=128 N=64 K=3136, 3-stage single-sync =================
__global__ __launch_bounds__(128, 4) void lowrank_mma(const float* __restrict__ Eb,
                                                      const float* __restrict__ Fb)
{
    extern __shared__ char sm[];
    uint32_t sb = smem_u32(sm);
    const int t = threadIdx.x, lane = t & 31, wid = t >> 5;
    const int wm = wid & 1, wn = wid >> 1;
    const int c0 = blockIdx.x * 64, b = blockIdx.y, which = blockIdx.z;

    const __half* A  = which ? g_F : g_E;
    const __half* Bm = which ? g_vT : g_kT;
    const float* bias = which ? Fb : Eb;

    auto issue = [&](int i) {
        uint32_t st = sb + SOFF + (i % 3) * G_STG;
        int k0 = i * 32;
#pragma unroll
        for (int l = 0; l < 4; l++) {
            int idx = t + 128 * l;
            int row = idx >> 2, cg = idx & 3;
            cpa16(st + row * ROWB + cg * 16, A + row * NSEQ + k0 + cg * 8);
        }
#pragma unroll
        for (int l = 0; l < 2; l++) {
            int idx = t + 128 * l;
            int row = idx >> 2, cg = idx & 3;
            cpa16(st + G_B + row * ROWB + cg * 16,
                  Bm + (b * DIM + c0 + row) * NSEQ + k0 + cg * 8);
        }
        CPA_COMMIT();
    };

    float acc[4][4][4] = {};
    issue(0); issue(1);
    for (int i = 0; i < 98; i++) {
        if (i + 1 < 98) { CPA_WAIT1(); } else { CPA_WAIT0(); }
        __syncthreads();                 // stage i ready; prev compute done
        if (i + 2 < 98) issue(i + 2);    // writes (i+2)%3, safe vs compute(i)
        chunk_64x32(sb + SOFF + (i % 3) * G_STG, wm, wn, lane, acc);
    }
    __syncthreads();

    if (which == 0) {
#pragma unroll
        for (int mf = 0; mf < 4; mf++)
#pragma unroll
            for (int rr = 0; rr < 2; rr++) {
                int r = wm * 64 + mf * 16 + (lane >> 2) + rr * 8;
                float bv = bias[r];
#pragma unroll
                for (int nf = 0; nf < 4; nf++)
#pragma unroll
                    for (int cp = 0; cp < 2; cp++) {
                        int c = wn * 32 + nf * 8 + (lane & 3) * 2 + cp;
                        *(__half*)(sm + SOFF + r * 144 + c * 2) =
                            __float2half(acc[mf][nf][rr * 2 + cp] + bv);
                    }
            }
        __syncthreads();
#pragma unroll
        for (int l = 0; l < 2; l++) {
            int idx = t + 128 * l;
            int r = idx >> 1, half = idx & 1;
            const uint4* src = (const uint4*)(sm + SOFF + r * 144 + half * 64);
            __half* dst = g_kl + (b * RLOW + r) * DIM + c0 + half * 32;
#pragma unroll
            for (int u = 0; u < 4; u++) ((uint4*)dst)[u] = src[u];
        }
    } else {
#pragma unroll
        for (int mf = 0; mf < 4; mf++)
#pragma unroll
            for (int rr = 0; rr < 2; rr++) {
                int r = wm * 64 + mf * 16 + (lane >> 2) + rr * 8;
                float bv = bias[r];
#pragma unroll
                for (int nf = 0; nf < 4; nf++)
#pragma unroll
                    for (int cp = 0; cp < 2; cp++) {
                        int c = wn * 32 + nf * 8 + (lane & 3) * 2 + cp;
                        *(__half*)(sm + SOFF + c * 272 + r * 2) =
                            __float2half(acc[mf][nf][rr * 2 + cp] + bv);
                    }
            }
        __syncthreads();
#pragma unroll
        for (int l = 0; l < 8; l++) {
            int idx = t + 128 * l;
            int c = idx >> 4, g = idx & 15;
            uint4 v = *(const uint4*)(sm + SOFF + c * 272 + g * 16);
            *(uint4*)(g_vlh + (b * DIM + c0 + c) * RLOW + g * 8) = v;
        }
    }
}

// ================= attention: R15-proven 128-thread, 1-term fp16 =================
#define AQ 0
#define AK 5120
#define AV 15360
#define ATT_SMEM 24064
__global__ __launch_bounds__(128) void attn_mma()
{
    extern __shared__ char sm[];
    uint32_t sb = smem_u32(sm);
    const int t = threadIdx.x, lane = t & 31, w = t >> 5;
    const int n0 = blockIdx.x * 64, hh = blockIdx.y, b = blockIdx.z;

    {
        const __half* qh = g_q + ((b * HEADS + hh) * NSEQ + n0) * HD;
#pragma unroll
        for (int l = 0; l < 2; l++) {
            int idx = t + 128 * l;
            int row = idx >> 2, cg = idx & 3;
            *(uint4*)(sm + AQ + row * 80 + cg * 16) = *(const uint4*)(qh + row * HD + cg * 8);
        }
        const __half* kh = g_kl + b * RLOW * DIM + hh * HD;
#pragma unroll
        for (int l = 0; l < 4; l++) {
            int idx = t + 128 * l;
            int row = idx >> 2, cg = idx & 3;
            *(uint4*)(sm + AK + row * 80 + cg * 16) = *(const uint4*)(kh + row * DIM + cg * 8);
        }
        const __half* vh = g_vlh + (b * DIM + hh * HD) * RLOW;
#pragma unroll
        for (int l = 0; l < 4; l++) {
            int idx = t + 128 * l;
            int row = idx >> 4, cg = idx & 15;
            *(uint4*)(sm + AV + row * 272 + cg * 16) = *(const uint4*)(vh + row * RLOW + cg * 8);
        }
    }
    __syncthreads();

    float acc[16][4] = {};
    {
        uint32_t qa = sb + AQ + (w * 16 + (lane & 15)) * 80 + ((lane >> 4) & 1) * 16;
        uint32_t ba = sb + AK + ((lane & 7) + ((lane >> 4) & 1) * 8) * 80 + ((lane >> 3) & 1) * 16;
#pragma unroll
        for (int ks = 0; ks < 2; ks++) {
            uint32_t aH[4];
            ldsm4(aH, qa + ks * 32);
#pragma unroll
            for (int np = 0; np < 8; np++) {
                uint32_t bh[4];
                ldsm4(bh, ba + np * 1280 + ks * 32);
                mma16816h(acc[2 * np], aH, bh[0], bh[1]);
                mma16816h(acc[2 * np + 1], aH, bh[2], bh[3]);
            }
        }
    }

    float m0 = -1e30f, m1 = -1e30f;
#pragma unroll
    for (int i = 0; i < 16; i++) {
        m0 = fmaxf(m0, fmaxf(acc[i][0], acc[i][1]));
        m1 = fmaxf(m1, fmaxf(acc[i][2], acc[i][3]));
    }
    m0 = fmaxf(m0, __shfl_xor_sync(0xffffffff, m0, 1));
    m0 = fmaxf(m0, __shfl_xor_sync(0xffffffff, m0, 2));
    m1 = fmaxf(m1, __shfl_xor_sync(0xffffffff, m1, 1));
    m1 = fmaxf(m1, __shfl_xor_sync(0xffffffff, m1, 2));
    float s0 = 0.f, s1 = 0.f;
#pragma unroll
    for (int i = 0; i < 16; i++) {
        acc[i][0] = __expf(acc[i][0] - m0); s0 += acc[i][0];
        acc[i][1] = __expf(acc[i][1] - m0); s0 += acc[i][1];
        acc[i][2] = __expf(acc[i][2] - m1); s1 += acc[i][2];
        acc[i][3] = __expf(acc[i][3] - m1); s1 += acc[i][3];
    }
    s0 += __shfl_xor_sync(0xffffffff, s0, 1);
    s0 += __shfl_xor_sync(0xffffffff, s0, 2);
    s1 += __shfl_xor_sync(0xffffffff, s1, 1);
    s1 += __shfl_xor_sync(0xffffffff, s1, 2);

    float oacc[4][4] = {};
    {
        uint32_t va = sb + AV + ((lane & 7) + ((lane >> 4) & 1) * 8) * 272 + ((lane >> 3) & 1) * 16;
#pragma unroll
        for (int kt = 0; kt < 8; kt++) {
            uint32_t ah[4];
            ah[0] = pack_half2(acc[2 * kt][0],     acc[2 * kt][1]);
            ah[1] = pack_half2(acc[2 * kt][2],     acc[2 * kt][3]);
            ah[2] = pack_half2(acc[2 * kt + 1][0], acc[2 * kt + 1][1]);
            ah[3] = pack_half2(acc[2 * kt + 1][2], acc[2 * kt + 1][3]);
#pragma unroll
            for (int np = 0; np < 2; np++) {
                uint32_t vh[4];
                ldsm4(vh, va + np * 16 * 272 + kt * 32);
                mma16816h(oacc[2 * np], ah, vh[0], vh[1]);
                mma16816h(oacc[2 * np + 1], ah, vh[2], vh[3]);
            }
        }
    }

    {
        float inv0 = 1.0f / s0, inv1 = 1.0f / s1;
        int gr = lane >> 2;
        int row0 = n0 + w * 16 + gr, row1 = row0 + 8;
        int cbase = hh * HD + (lane & 3) * 2;
#pragma unroll
        for (int nf = 0; nf < 4; nf++) {
            int col = cbase + nf * 8;
            *(uint32_t*)(g_a + (b * NSEQ + row0) * DIM + col) =
                pack_half2(oacc[nf][0] * inv0, oacc[nf][1] * inv0);
            *(uint32_t*)(g_a + (b * NSEQ + row1) * DIM + col) =
                pack_half2(oacc[nf][2] * inv1, oacc[nf][3] * inv1);
        }
    }
}

// ================= proj: M=128 N=64 K=192, 128 threads (SMEM_PROJ) =================
__global__ __launch_bounds__(128, 4) void proj_mma(const float* __restrict__ bias,
                                                   float* __restrict__ out)
{
    extern __shared__ char sm[];
    uint32_t sb = smem_u32(sm);
    const int t = threadIdx.x, lane = t & 31, wid = t >> 5;
    const int wm = wid & 1, wn = wid >> 1;
    const int m0 = blockIdx.x * 128, j0 = blockIdx.y * 64;

    auto issue = [&](int i) {
        uint32_t st = sb + SOFF + (i & 1) * G_STG;
        int k0 = i * 32;
#pragma unroll
        for (int l = 0; l < 4; l++) {
            int idx = t + 128 * l;
            int row = idx >> 2, cg = idx & 3;
            cpa16(st + row * ROWB + cg * 16, g_a + (m0 + row) * DIM + k0 + cg * 8);
        }
#pragma unroll
        for (int l = 0; l < 2; l++) {
            int idx = t + 128 * l;
            int row = idx >> 2, cg = idx & 3;
            cpa16(st + G_B + row * ROWB + cg * 16, g_wp + (j0 + row) * DIM + k0 + cg * 8);
        }
        CPA_COMMIT();
    };

    float acc[4][4][4] = {};
    issue(0);
    for (int i = 0; i < 6; i++) {
        if (i < 5) { issue(i + 1); CPA_WAIT1(); } else { CPA_WAIT0(); }
        __syncthreads();
        chunk_64x32(sb + SOFF + (i & 1) * G_STG, wm, wn, lane, acc);
        __syncthreads();
    }

#pragma unroll
    for (int mf = 0; mf < 4; mf++)
#pragma unroll
        for (int rr = 0; rr < 2; rr++) {
            int ml = wm * 64 + mf * 16 + (lane >> 2) + rr * 8;
#pragma unroll
            for (int nf = 0; nf < 4; nf++)
#pragma unroll
                for (int cp = 0; cp < 2; cp++) {
                    int c = wn * 32 + nf * 8 + (lane & 3) * 2 + cp;
                    *(float*)(sm + SOFF + ml * 272 + c * 4) =
                        acc[mf][nf][rr * 2 + cp] + bias[j0 + c];
                }
        }
    __syncthreads();
#pragma unroll
    for (int l = 0; l < 16; l++) {
        int idx = t + 128 * l;
        int row = idx >> 4, g = idx & 15;
        uint4 v = *(const uint4*)(sm + SOFF + row * 272 + g * 16);
        *(uint4*)(out + (m0 + row) * DIM + j0 + g * 4) = v;
    }
}

// ================= host =================
extern "C" void kernel_launch(void* const* d_in, const int* in_sizes, int n_in,
                              void* d_out, int out_size)
{
    const float* x      = (const float*)d_in[0];
    const float* qkv_w  = (const float*)d_in[1];
    const float* qkv_b  = (const float*)d_in[2];
    const float* E_w    = (const float*)d_in[3];
    const float* E_b    = (const float*)d_in[4];
    const float* F_w    = (const float*)d_in[5];
    const float* F_b    = (const float*)d_in[6];
    const float* proj_w = (const float*)d_in[7];
    const float* proj_b = (const float*)d_in[8];
    float* out = (float*)d_out;

    cudaFuncSetAttribute(qkv_mma, cudaFuncAttributeMaxDynamicSharedMemorySize, SMEM_G);
    cudaFuncSetAttribute(lowrank_mma, cudaFuncAttributeMaxDynamicSharedMemorySize, SMEM_LR);
    cudaFuncSetAttribute(proj_mma, cudaFuncAttributeMaxDynamicSharedMemorySize, SMEM_PROJ);
    cudaFuncSetAttribute(attn_mma, cudaFuncAttributeMaxDynamicSharedMemorySize, ATT_SMEM);

    split_all<<<(N4TOT + 255) / 256, 256>>>(x, qkv_w, E_w, F_w, proj_w);
    qkv_mma<<<dim3(MTOT / 128, 9), 128, SMEM_G>>>(qkv_b);
    lowrank_mma<<<dim3(3, BATCH, 2), 128, SMEM_LR>>>(E_b, F_b);
    attn_mma<<<dim3(NSEQ / 64, HEADS, BATCH), 128, ATT_SMEM>>>();
    proj_mma<<<dim3(MTOT / 128, 3), 128, SMEM_PROJ>>>(proj_b, out);
}